// round 9
// baseline (speedup 1.0000x reference)
#include <cuda_runtime.h>

#define N_NODES 50000
#define N_EDGES 800000

// ---------------- scratch (static device globals; no allocations) ----------------
__device__ __align__(16) float    g_tab[576];                    // al|ar|ae|k1|cl (5x64), u2(128)@320, v2(128)@448
__device__ __align__(16) unsigned g_amax1[N_NODES * 8];
__device__ __align__(16) float    g_den1[N_NODES * 8];
__device__ __align__(16) float    g_num1[N_NODES * 8];
__device__ __align__(16) float    g_alpha1[(size_t)N_EDGES * 8]; // 25.6 MB
__device__ __align__(16) float    g_xl2[(size_t)N_NODES * 128];  // 25.6 MB
__device__ __align__(16) float    g_xr2[(size_t)N_NODES * 128];  // 25.6 MB
__device__ __align__(16) float    g_alpha2[N_EDGES];
__device__ __align__(16) unsigned g_amax2[N_NODES];
__device__ __align__(16) float    g_den2[N_NODES];
__device__ __align__(16) float    g_num2[(size_t)N_NODES * 128]; // 25.6 MB
__device__ __align__(16) float    g_s[N_NODES];
__device__ __align__(16) float    g_t[N_NODES];

// order-preserving float<->uint map for atomicMax on signed floats
__device__ __forceinline__ unsigned f2u(float f) {
    unsigned u = __float_as_uint(f);
    return (u & 0x80000000u) ? ~u : (u | 0x80000000u);
}
__device__ __forceinline__ float u2f(unsigned u) {
    return (u & 0x80000000u) ? __uint_as_float(u ^ 0x80000000u) : __uint_as_float(~u);
}

// ---------------- kernel 0: derived rank-1 vectors ----------------
__global__ void k_derive(const float* __restrict__ W_em, const float* __restrict__ b_em,
                         const float* __restrict__ W0,   const float* __restrict__ b0,
                         const float* __restrict__ Wl1,  const float* __restrict__ bl1,
                         const float* __restrict__ Wr1,  const float* __restrict__ br1,
                         const float* __restrict__ We1,  const float* __restrict__ We2) {
    int c = threadIdx.x;  // 0..127
    if (c < 64) {
        float al = 0.f, cl = 0.f, ar = 0.f, cr = 0.f, ae = 0.f, ce = 0.f;
        for (int j = 0; j < 128; j++) {
            float w0 = W0[j], bb = b0[j], we = W_em[j], be = b_em[j];
            float l = Wl1[j * 64 + c], r = Wr1[j * 64 + c], ev = We1[j * 64 + c];
            al = fmaf(w0, l, al); cl = fmaf(bb, l, cl);
            ar = fmaf(w0, r, ar); cr = fmaf(bb, r, cr);
            ae = fmaf(we, ev, ae); ce = fmaf(be, ev, ce);
        }
        cl += bl1[c]; cr += br1[c];
        g_tab[c]       = al;
        g_tab[64 + c]  = ar;
        g_tab[128 + c] = ae;
        g_tab[192 + c] = cl + cr + ce;   // constant inside leaky_relu
        g_tab[256 + c] = cl;             // needed for out1 = al*S1 + cl*S0
    }
    float u = 0.f, v = 0.f;
    for (int j = 0; j < 128; j++) {
        float w = We2[j * 128 + c];
        u = fmaf(W_em[j], w, u);
        v = fmaf(b_em[j], w, v);
    }
    g_tab[320 + c] = u;
    g_tab[448 + c] = v;
}

// ---------------- kernel 1: zero the accumulators ----------------
__global__ void k_init(int n) {
    int stride = gridDim.x * blockDim.x;
    int tot = n * 128;
    for (int i = blockIdx.x * blockDim.x + threadIdx.x; i < tot; i += stride) {
        g_num2[i] = 0.f;
        if (i < n * 8) { g_amax1[i] = 0u; g_den1[i] = 0.f; g_num1[i] = 0.f; }
        if (i < n)     { g_amax2[i] = 0u; g_den2[i] = 0.f; }
    }
}

// ---------------- layer 1, pass A: per-edge raw attention + segment max ----------------
__global__ __launch_bounds__(256) void k_edge1a(const float* __restrict__ x,
                                                const int* __restrict__ ei,
                                                const float* __restrict__ eattr,
                                                const float* __restrict__ att1, int E) {
    __shared__ float s_al[64], s_ar[64], s_ae[64], s_k1[64], s_at[64];
    int tid = threadIdx.x;
    if (tid < 64) {
        s_al[tid] = g_tab[tid];
        s_ar[tid] = g_tab[64 + tid];
        s_ae[tid] = g_tab[128 + tid];
        s_k1[tid] = g_tab[192 + tid];
        s_at[tid] = att1[tid];
    }
    __syncthreads();
    int e = blockIdx.x * blockDim.x + tid;
    if (e >= E) return;
    int sn = ei[e], dn = ei[E + e];        // edge_index is int32 (JAX x64 disabled)
    float xs = x[sn], xd = x[dn], ea = eattr[e];
    float a[8];
#pragma unroll
    for (int h = 0; h < 8; h++) {
        float acc = 0.f;
#pragma unroll
        for (int c = 0; c < 8; c++) {
            int i = h * 8 + c;
            float z = fmaf(xs, s_al[i], fmaf(xd, s_ar[i], fmaf(ea, s_ae[i], s_k1[i])));
            z = z > 0.f ? z : 0.2f * z;
            acc = fmaf(z, s_at[i], acc);
        }
        a[h] = acc;
        atomicMax(&g_amax1[(size_t)dn * 8 + h], f2u(acc));
    }
    float4* ap = (float4*)&g_alpha1[(size_t)e * 8];
    ap[0] = make_float4(a[0], a[1], a[2], a[3]);
    ap[1] = make_float4(a[4], a[5], a[6], a[7]);
}

// ---------------- layer 1, pass B: exp + fused numerator/denominator ----------------
__global__ __launch_bounds__(256) void k_edge1b(const float* __restrict__ x,
                                                const int* __restrict__ ei, int E) {
    int e = blockIdx.x * blockDim.x + threadIdx.x;
    if (e >= E) return;
    int sn = ei[e], dn = ei[E + e];
    float xs = x[sn];
    const float4* ap = (const float4*)&g_alpha1[(size_t)e * 8];
    float4 a0 = ap[0], a1 = ap[1];
    const uint4* mp = (const uint4*)&g_amax1[(size_t)dn * 8];
    uint4 m0 = mp[0], m1 = mp[1];
    float ex[8];
    ex[0] = __expf(a0.x - u2f(m0.x)); ex[1] = __expf(a0.y - u2f(m0.y));
    ex[2] = __expf(a0.z - u2f(m0.z)); ex[3] = __expf(a0.w - u2f(m0.w));
    ex[4] = __expf(a1.x - u2f(m1.x)); ex[5] = __expf(a1.y - u2f(m1.y));
    ex[6] = __expf(a1.z - u2f(m1.z)); ex[7] = __expf(a1.w - u2f(m1.w));
    float* dp = &g_den1[(size_t)dn * 8];
    float* np = &g_num1[(size_t)dn * 8];
#pragma unroll
    for (int h = 0; h < 8; h++) {
        atomicAdd(dp + h, ex[h]);          // return unused -> RED
        atomicAdd(np + h, ex[h] * xs);
    }
}

// ---------------- node pass: h1 = ELU(out1), then xl2/xr2 = h1 @ Wl2/Wr2 ----------------
__global__ __launch_bounds__(256) void k_node1(const float* __restrict__ Wl2, const float* __restrict__ bl2,
                                               const float* __restrict__ Wr2, const float* __restrict__ br2,
                                               const float* __restrict__ bias1, int N) {
    __shared__ float s_h[128 * 64];
    __shared__ float s_al[64], s_cl[64], s_b1[64];
    int tid = threadIdx.x;
    if (tid < 64) { s_al[tid] = g_tab[tid]; s_cl[tid] = g_tab[256 + tid]; s_b1[tid] = bias1[tid]; }
    int half = tid >> 7, k = tid & 127;
    const float* W = half ? Wr2 : Wl2;
    float bcol = half ? br2[k] : bl2[k];
    float wreg[64];
#pragma unroll
    for (int j = 0; j < 64; j++) wreg[j] = W[j * 128 + k];   // weight column in registers
    __syncthreads();                                          // s_al/s_cl/s_b1 visible to ALL threads
    int n0 = blockIdx.x * 128;
    int nt = min(128, N - n0);
    for (int idx = tid; idx < nt * 64; idx += 256) {
        int nl = idx >> 6, hc = idx & 63, h = hc >> 3;
        int n = n0 + nl;
        float den = g_den1[(size_t)n * 8 + h];
        float dm = fmaxf(den, 1e-16f);
        float S1 = g_num1[(size_t)n * 8 + h] / dm;
        float S0 = den / dm;                                  // 1 if node has edges, else 0
        float o = fmaf(s_al[hc], S1, s_cl[hc] * S0) + s_b1[hc];
        s_h[idx] = o > 0.f ? o : expm1f(o);                   // ELU (keep precise)
    }
    __syncthreads();
    float* dst = half ? g_xr2 : g_xl2;
    for (int nl = 0; nl < nt; nl++) {
        float acc = bcol;
#pragma unroll
        for (int j = 0; j < 64; j++) acc = fmaf(s_h[nl * 64 + j], wreg[j], acc);
        dst[(size_t)(n0 + nl) * 128 + k] = acc;
    }
}

// ---------------- layer 2, pass A: raw attention (warp per edge, broadcast loads) ----------------
__global__ __launch_bounds__(256) void k_edge2a(const int* __restrict__ ei,
                                                const float* __restrict__ eattr,
                                                const float* __restrict__ att2, int E) {
    int gt = blockIdx.x * blockDim.x + threadIdx.x;
    int lane = threadIdx.x & 31;
    int gw = gt >> 5;
    int nw = (gridDim.x * blockDim.x) >> 5;
    int c = lane * 4;
    float4 u2 = *(const float4*)&g_tab[320 + c];
    float4 v2 = *(const float4*)&g_tab[448 + c];
    float4 at = *(const float4*)&att2[c];
    for (int e = gw; e < E; e += nw) {
        // same-address loads across the warp -> single broadcast wavefront, no shfl chain
        int sd = ei[e];
        int dd = ei[E + e];
        float ea = eattr[e];
        float4 xl = *(const float4*)&g_xl2[(size_t)sd * 128 + c];
        float4 xr = *(const float4*)&g_xr2[(size_t)dd * 128 + c];
        float z0 = xl.x + xr.x + fmaf(ea, u2.x, v2.x); z0 = z0 > 0.f ? z0 : 0.2f * z0;
        float z1 = xl.y + xr.y + fmaf(ea, u2.y, v2.y); z1 = z1 > 0.f ? z1 : 0.2f * z1;
        float z2 = xl.z + xr.z + fmaf(ea, u2.z, v2.z); z2 = z2 > 0.f ? z2 : 0.2f * z2;
        float z3 = xl.w + xr.w + fmaf(ea, u2.w, v2.w); z3 = z3 > 0.f ? z3 : 0.2f * z3;
        float acc = fmaf(z0, at.x, fmaf(z1, at.y, fmaf(z2, at.z, z3 * at.w)));
#pragma unroll
        for (int o = 16; o > 0; o >>= 1) acc += __shfl_xor_sync(0xffffffffu, acc, o);
        if (lane == 0) {
            g_alpha2[e] = acc;
            atomicMax(&g_amax2[dd], f2u(acc));
        }
    }
}

// ---------------- layer 2, pass B: exp + weighted scatter (warp per edge, broadcast loads) ----------------
__global__ __launch_bounds__(256) void k_edge2b(const int* __restrict__ ei, int E) {
    int gt = blockIdx.x * blockDim.x + threadIdx.x;
    int lane = threadIdx.x & 31;
    int gw = gt >> 5;
    int nw = (gridDim.x * blockDim.x) >> 5;
    int c = lane * 4;
    for (int e = gw; e < E; e += nw) {
        // same-address loads across the warp -> broadcast; redundant __expf is 1 MUFU/lane
        int sd = ei[e];
        int dd = ei[E + e];
        float mx = u2f(g_amax2[dd]);
        float ex = __expf(g_alpha2[e] - mx);
        if (lane == 0) atomicAdd(&g_den2[dd], ex);   // exactly one den-RED per edge
        float4 xl = *(const float4*)&g_xl2[(size_t)sd * 128 + c];
        float* np = &g_num2[(size_t)dd * 128 + c];
        atomicAdd(np,     ex * xl.x);      // return unused -> RED; one 16B segment per lane
        atomicAdd(np + 1, ex * xl.y);
        atomicAdd(np + 2, ex * xl.z);
        atomicAdd(np + 3, ex * xl.w);
    }
}

// ---------------- node pass 2: h2 = num2/den2 + bias2; s = h2.Wd_top, t = h2.Wd_bot ----------------
__global__ __launch_bounds__(256) void k_node2(const float* __restrict__ bias2,
                                               const float* __restrict__ Wd, int N) {
    int gt = blockIdx.x * blockDim.x + threadIdx.x;
    int lane = threadIdx.x & 31;
    int n = gt >> 5;
    if (n >= N) return;
    int c = lane * 4;
    float4 b2 = *(const float4*)&bias2[c];
    float4 w0 = *(const float4*)&Wd[c];
    float4 w1 = *(const float4*)&Wd[128 + c];
    float den = g_den2[n];
    float inv = 1.f / fmaxf(den, 1e-16f);
    float4 nm = *(const float4*)&g_num2[(size_t)n * 128 + c];
    float h0 = fmaf(nm.x, inv, b2.x), h1 = fmaf(nm.y, inv, b2.y);
    float h2 = fmaf(nm.z, inv, b2.z), h3 = fmaf(nm.w, inv, b2.w);
    float sa = fmaf(h0, w0.x, fmaf(h1, w0.y, fmaf(h2, w0.z, h3 * w0.w)));
    float ta = fmaf(h0, w1.x, fmaf(h1, w1.y, fmaf(h2, w1.z, h3 * w1.w)));
#pragma unroll
    for (int o = 16; o > 0; o >>= 1) {
        sa += __shfl_xor_sync(0xffffffffu, sa, o);
        ta += __shfl_xor_sync(0xffffffffu, ta, o);
    }
    if (lane == 0) { g_s[n] = sa; g_t[n] = ta; }
}

// ---------------- final: out[e] = s[src] + t[dst] + bd ----------------
__global__ __launch_bounds__(256) void k_final(const int* __restrict__ ei,
                                               const float* __restrict__ bd,
                                               float* __restrict__ out, int E) {
    int e = blockIdx.x * blockDim.x + threadIdx.x;
    if (e >= E) return;
    out[e] = g_s[ei[e]] + g_t[ei[E + e]] + bd[0];
}

// ---------------- launch ----------------
extern "C" void kernel_launch(void* const* d_in, const int* in_sizes, int n_in,
                              void* d_out, int out_size) {
    const float* x     = (const float*)d_in[0];
    const int*   ei    = (const int*)d_in[1];      // int32: JAX demotes int64 without x64 mode
    const float* eattr = (const float*)d_in[2];
    const float* W_em = (const float*)d_in[3];  const float* b_em = (const float*)d_in[4];
    const float* W0   = (const float*)d_in[5];  const float* b0   = (const float*)d_in[6];
    const float* Wl1  = (const float*)d_in[7];  const float* bl1  = (const float*)d_in[8];
    const float* Wr1  = (const float*)d_in[9];  const float* br1  = (const float*)d_in[10];
    const float* We1  = (const float*)d_in[11]; const float* att1 = (const float*)d_in[12];
    const float* bias1= (const float*)d_in[13];
    const float* Wl2  = (const float*)d_in[14]; const float* bl2  = (const float*)d_in[15];
    const float* Wr2  = (const float*)d_in[16]; const float* br2  = (const float*)d_in[17];
    const float* We2  = (const float*)d_in[18]; const float* att2 = (const float*)d_in[19];
    const float* bias2= (const float*)d_in[20];
    const float* Wd   = (const float*)d_in[21]; const float* bd   = (const float*)d_in[22];
    int N = in_sizes[0];          // x is [N,1]
    int E = in_sizes[2];          // edge_attr is [E,1]
    float* out = (float*)d_out;

    k_derive<<<1, 128>>>(W_em, b_em, W0, b0, Wl1, bl1, Wr1, br1, We1, We2);
    k_init<<<4096, 256>>>(N);
    k_edge1a<<<(E + 255) / 256, 256>>>(x, ei, eattr, att1, E);
    k_edge1b<<<(E + 255) / 256, 256>>>(x, ei, E);
    k_node1<<<(N + 127) / 128, 256>>>(Wl2, bl2, Wr2, br2, bias1, N);
    k_edge2a<<<2048, 256>>>(ei, eattr, att2, E);
    k_edge2b<<<2048, 256>>>(ei, E);
    k_node2<<<(N * 32 + 255) / 256, 256>>>(bias2, Wd, N);
    k_final<<<(E + 255) / 256, 256>>>(ei, bd, out, E);
}

// round 11
// speedup vs baseline: 2.3314x; 2.3314x over previous
#include <cuda_runtime.h>

#define N_NODES 50000
#define N_EDGES 800000

// ---------------- scratch (static device globals; no allocations) ----------------
__device__ __align__(16) float g_tab[576];                    // al|ar|ae|k1|cl (5x64), u2(128)@320, v2(128)@448
__device__ __align__(16) float g_den1[N_NODES * 8];
__device__ __align__(16) float g_num1[N_NODES * 8];
__device__ __align__(16) float g_xl2[(size_t)N_NODES * 128];  // 25.6 MB
__device__ __align__(16) float g_xr2[(size_t)N_NODES * 128];  // 25.6 MB
__device__ __align__(16) float g_s[N_NODES];
__device__ __align__(16) float g_t[N_NODES];
// CSR by destination
__device__ int   g_cnt[N_NODES];
__device__ int   g_fill[N_NODES];
__device__ int   g_rowptr[N_NODES + 1];
__device__ int   g_esrc[N_EDGES];                             // src node per CSR slot
__device__ __align__(16) float g_ea[N_EDGES];                 // edge_attr per CSR slot

// ---------------- kernel 0: derived rank-1 vectors ----------------
__global__ void k_derive(const float* __restrict__ W_em, const float* __restrict__ b_em,
                         const float* __restrict__ W0,   const float* __restrict__ b0,
                         const float* __restrict__ Wl1,  const float* __restrict__ bl1,
                         const float* __restrict__ Wr1,  const float* __restrict__ br1,
                         const float* __restrict__ We1,  const float* __restrict__ We2) {
    int c = threadIdx.x;  // 0..127
    if (c < 64) {
        float al = 0.f, cl = 0.f, ar = 0.f, cr = 0.f, ae = 0.f, ce = 0.f;
        for (int j = 0; j < 128; j++) {
            float w0 = W0[j], bb = b0[j], we = W_em[j], be = b_em[j];
            float l = Wl1[j * 64 + c], r = Wr1[j * 64 + c], ev = We1[j * 64 + c];
            al = fmaf(w0, l, al); cl = fmaf(bb, l, cl);
            ar = fmaf(w0, r, ar); cr = fmaf(bb, r, cr);
            ae = fmaf(we, ev, ae); ce = fmaf(be, ev, ce);
        }
        cl += bl1[c]; cr += br1[c];
        g_tab[c]       = al;
        g_tab[64 + c]  = ar;
        g_tab[128 + c] = ae;
        g_tab[192 + c] = cl + cr + ce;   // constant inside leaky_relu
        g_tab[256 + c] = cl;             // out1 = al*S1 + cl*S0
    }
    float u = 0.f, v = 0.f;
    for (int j = 0; j < 128; j++) {
        float w = We2[j * 128 + c];
        u = fmaf(W_em[j], w, u);
        v = fmaf(b_em[j], w, v);
    }
    g_tab[320 + c] = u;
    g_tab[448 + c] = v;
}

// ---------------- CSR build ----------------
__global__ void k_zero(int n) {
    int i = blockIdx.x * blockDim.x + threadIdx.x;
    if (i < n) { g_cnt[i] = 0; g_fill[i] = 0; }
}

__global__ void k_count(const int* __restrict__ ei, int E) {
    int e = blockIdx.x * blockDim.x + threadIdx.x;
    if (e < E) atomicAdd(&g_cnt[ei[E + e]], 1);
}

// single-block exclusive scan over g_cnt -> g_rowptr (warp-shuffle based)
__global__ __launch_bounds__(1024) void k_scan(int n) {
    __shared__ int wsum[32];
    __shared__ int sh_carry, sh_total;
    int tid = threadIdx.x, lane = tid & 31, wid = tid >> 5;
    if (tid == 0) sh_carry = 0;
    __syncthreads();
    for (int base = 0; base < n; base += 1024) {
        int i = base + tid;
        int v = (i < n) ? g_cnt[i] : 0;
        int incl = v;
#pragma unroll
        for (int o = 1; o < 32; o <<= 1) {
            int t = __shfl_up_sync(0xffffffffu, incl, o);
            if (lane >= o) incl += t;
        }
        if (lane == 31) wsum[wid] = incl;
        __syncthreads();
        if (wid == 0) {
            int wv = wsum[lane];
            int wincl = wv;
#pragma unroll
            for (int o = 1; o < 32; o <<= 1) {
                int t = __shfl_up_sync(0xffffffffu, wincl, o);
                if (lane >= o) wincl += t;
            }
            wsum[lane] = wincl - wv;            // exclusive warp offset
            if (lane == 31) sh_total = wincl;   // chunk total
        }
        __syncthreads();
        if (i < n) g_rowptr[i] = sh_carry + wsum[wid] + incl - v;
        __syncthreads();
        if (tid == 0) sh_carry += sh_total;
        __syncthreads();
    }
    if (tid == 0) g_rowptr[n] = sh_carry;
}

__global__ void k_scatter(const int* __restrict__ ei, const float* __restrict__ eattr, int E) {
    int e = blockIdx.x * blockDim.x + threadIdx.x;
    if (e >= E) return;
    int dst = ei[E + e];
    int pos = g_rowptr[dst] + atomicAdd(&g_fill[dst], 1);
    g_esrc[pos] = ei[e];
    g_ea[pos]   = eattr[e];
}

// ---------------- layer 1 fused: online softmax per (node, head) lane ----------------
__global__ __launch_bounds__(256) void k_seg1(const float* __restrict__ x,
                                              const float* __restrict__ att1, int N) {
    int gl = blockIdx.x * blockDim.x + threadIdx.x;  // lane id in [0, N*8)
    int node = gl >> 3;
    int head = gl & 7;
    if (node >= N) return;
    // coefficients for this head (8 channels) in registers
    float al[8], ar[8], ae[8], k1[8], at[8];
#pragma unroll
    for (int c = 0; c < 8; c++) {
        int i = head * 8 + c;
        al[c] = g_tab[i];
        ar[c] = g_tab[64 + i];
        ae[c] = g_tab[128 + i];
        k1[c] = g_tab[192 + i];
        at[c] = att1[i];
    }
    float xd = x[node];
    int beg = g_rowptr[node], end = g_rowptr[node + 1];
    float mx = -1e30f, den = 0.f, num = 0.f;
    for (int j = beg; j < end; j++) {
        int s = g_esrc[j];
        float ea = g_ea[j];
        float xs = x[s];
        float a = 0.f;
#pragma unroll
        for (int c = 0; c < 8; c++) {
            float z = fmaf(xs, al[c], fmaf(xd, ar[c], fmaf(ea, ae[c], k1[c])));
            z = z > 0.f ? z : 0.2f * z;
            a = fmaf(z, at[c], a);
        }
        float mnew = fmaxf(mx, a);
        float corr = __expf(mx - mnew);   // 0 on first edge (mx=-1e30)
        float ex   = __expf(a - mnew);
        den = den * corr + ex;
        num = num * corr + ex * xs;
        mx = mnew;
    }
    g_den1[node * 8 + head] = den;
    g_num1[node * 8 + head] = num;
}

// ---------------- node pass: h1 = ELU(out1), then xl2/xr2 = h1 @ Wl2/Wr2 ----------------
__global__ __launch_bounds__(256) void k_node1(const float* __restrict__ Wl2, const float* __restrict__ bl2,
                                               const float* __restrict__ Wr2, const float* __restrict__ br2,
                                               const float* __restrict__ bias1, int N) {
    __shared__ float s_h[128 * 64];
    __shared__ float s_al[64], s_cl[64], s_b1[64];
    int tid = threadIdx.x;
    if (tid < 64) { s_al[tid] = g_tab[tid]; s_cl[tid] = g_tab[256 + tid]; s_b1[tid] = bias1[tid]; }
    int half = tid >> 7, k = tid & 127;
    const float* W = half ? Wr2 : Wl2;
    float bcol = half ? br2[k] : bl2[k];
    float wreg[64];
#pragma unroll
    for (int j = 0; j < 64; j++) wreg[j] = W[j * 128 + k];   // weight column in registers
    __syncthreads();
    int n0 = blockIdx.x * 128;
    int nt = min(128, N - n0);
    for (int idx = tid; idx < nt * 64; idx += 256) {
        int nl = idx >> 6, hc = idx & 63, h = hc >> 3;
        int n = n0 + nl;
        float den = g_den1[(size_t)n * 8 + h];
        float dm = fmaxf(den, 1e-16f);
        float S1 = g_num1[(size_t)n * 8 + h] / dm;
        float S0 = den / dm;                                  // 1 if node has edges, else 0
        float o = fmaf(s_al[hc], S1, s_cl[hc] * S0) + s_b1[hc];
        s_h[idx] = o > 0.f ? o : expm1f(o);                   // ELU
    }
    __syncthreads();
    float* dst = half ? g_xr2 : g_xl2;
    for (int nl = 0; nl < nt; nl++) {
        float acc = bcol;
#pragma unroll
        for (int j = 0; j < 64; j++) acc = fmaf(s_h[nl * 64 + j], wreg[j], acc);
        dst[(size_t)(n0 + nl) * 128 + k] = acc;
    }
}

// ---------------- layer 2 fused: warp per node, online softmax, epilogue -> s,t ----------------
__global__ __launch_bounds__(256) void k_seg2(const float* __restrict__ att2,
                                              const float* __restrict__ bias2,
                                              const float* __restrict__ Wd, int N) {
    int wid = (blockIdx.x * blockDim.x + threadIdx.x) >> 5;
    int lane = threadIdx.x & 31;
    if (wid >= N) return;
    int n = wid;
    int c = lane * 4;
    float4 u2  = *(const float4*)&g_tab[320 + c];
    float4 v2  = *(const float4*)&g_tab[448 + c];
    float4 at  = *(const float4*)&att2[c];
    float4 xr  = *(const float4*)&g_xr2[(size_t)n * 128 + c];
    float4 xrv = make_float4(xr.x + v2.x, xr.y + v2.y, xr.z + v2.z, xr.w + v2.w);
    int beg = g_rowptr[n], end = g_rowptr[n + 1];
    float mx = -1e30f, den = 0.f;
    float4 acc = make_float4(0.f, 0.f, 0.f, 0.f);
    for (int j = beg; j < end; j++) {
        int s = g_esrc[j];          // broadcast loads (same addr across warp)
        float ea = g_ea[j];
        float4 xl = *(const float4*)&g_xl2[(size_t)s * 128 + c];
        float z0 = xl.x + fmaf(ea, u2.x, xrv.x); z0 = z0 > 0.f ? z0 : 0.2f * z0;
        float z1 = xl.y + fmaf(ea, u2.y, xrv.y); z1 = z1 > 0.f ? z1 : 0.2f * z1;
        float z2 = xl.z + fmaf(ea, u2.z, xrv.z); z2 = z2 > 0.f ? z2 : 0.2f * z2;
        float z3 = xl.w + fmaf(ea, u2.w, xrv.w); z3 = z3 > 0.f ? z3 : 0.2f * z3;
        float p = fmaf(z0, at.x, fmaf(z1, at.y, fmaf(z2, at.z, z3 * at.w)));
#pragma unroll
        for (int o = 16; o > 0; o >>= 1) p += __shfl_xor_sync(0xffffffffu, p, o);
        float mnew = fmaxf(mx, p);
        float corr = __expf(mx - mnew);
        float ex   = __expf(p - mnew);
        den   = den * corr + ex;
        acc.x = fmaf(acc.x, corr, ex * xl.x);
        acc.y = fmaf(acc.y, corr, ex * xl.y);
        acc.z = fmaf(acc.z, corr, ex * xl.z);
        acc.w = fmaf(acc.w, corr, ex * xl.w);
        mx = mnew;
    }
    float inv = 1.f / fmaxf(den, 1e-16f);
    float4 b2 = *(const float4*)&bias2[c];
    float4 w0 = *(const float4*)&Wd[c];
    float4 w1 = *(const float4*)&Wd[128 + c];
    float h0 = fmaf(acc.x, inv, b2.x), h1 = fmaf(acc.y, inv, b2.y);
    float h2 = fmaf(acc.z, inv, b2.z), h3 = fmaf(acc.w, inv, b2.w);
    float sa = fmaf(h0, w0.x, fmaf(h1, w0.y, fmaf(h2, w0.z, h3 * w0.w)));
    float ta = fmaf(h0, w1.x, fmaf(h1, w1.y, fmaf(h2, w1.z, h3 * w1.w)));
#pragma unroll
    for (int o = 16; o > 0; o >>= 1) {
        sa += __shfl_xor_sync(0xffffffffu, sa, o);
        ta += __shfl_xor_sync(0xffffffffu, ta, o);
    }
    if (lane == 0) { g_s[n] = sa; g_t[n] = ta; }
}

// ---------------- final: out[e] = s[src] + t[dst] + bd ----------------
__global__ __launch_bounds__(256) void k_final(const int* __restrict__ ei,
                                               const float* __restrict__ bd,
                                               float* __restrict__ out, int E) {
    int e = blockIdx.x * blockDim.x + threadIdx.x;
    if (e >= E) return;
    out[e] = g_s[ei[e]] + g_t[ei[E + e]] + bd[0];
}

// ---------------- launch ----------------
extern "C" void kernel_launch(void* const* d_in, const int* in_sizes, int n_in,
                              void* d_out, int out_size) {
    const float* x     = (const float*)d_in[0];
    const int*   ei    = (const int*)d_in[1];      // int32 (JAX x64 disabled)
    const float* eattr = (const float*)d_in[2];
    const float* W_em = (const float*)d_in[3];  const float* b_em = (const float*)d_in[4];
    const float* W0   = (const float*)d_in[5];  const float* b0   = (const float*)d_in[6];
    const float* Wl1  = (const float*)d_in[7];  const float* bl1  = (const float*)d_in[8];
    const float* Wr1  = (const float*)d_in[9];  const float* br1  = (const float*)d_in[10];
    const float* We1  = (const float*)d_in[11]; const float* att1 = (const float*)d_in[12];
    const float* bias1= (const float*)d_in[13];
    const float* Wl2  = (const float*)d_in[14]; const float* bl2  = (const float*)d_in[15];
    const float* Wr2  = (const float*)d_in[16]; const float* br2  = (const float*)d_in[17];
    const float* We2  = (const float*)d_in[18]; const float* att2 = (const float*)d_in[19];
    const float* bias2= (const float*)d_in[20];
    const float* Wd   = (const float*)d_in[21]; const float* bd   = (const float*)d_in[22];
    int N = in_sizes[0];          // x is [N,1]
    int E = in_sizes[2];          // edge_attr is [E,1]
    float* out = (float*)d_out;

    k_zero<<<(N + 255) / 256, 256>>>(N);
    k_derive<<<1, 128>>>(W_em, b_em, W0, b0, Wl1, bl1, Wr1, br1, We1, We2);
    k_count<<<(E + 255) / 256, 256>>>(ei, E);
    k_scan<<<1, 1024>>>(N);
    k_scatter<<<(E + 255) / 256, 256>>>(ei, eattr, E);
    k_seg1<<<(N * 8 + 255) / 256, 256>>>(x, att1, N);
    k_node1<<<(N + 127) / 128, 256>>>(Wl2, bl2, Wr2, br2, bias1, N);
    k_seg2<<<(N + 7) / 8, 256>>>(att2, bias2, Wd, N);
    k_final<<<(E + 255) / 256, 256>>>(ei, bd, out, E);
}

// round 14
// speedup vs baseline: 2.6216x; 1.1245x over previous
#include <cuda_runtime.h>

#define N_NODES 50000
#define N_EDGES 800000

// ---------------- scratch (static device globals; no allocations) ----------------
__device__ __align__(16) float g_tab[576];                    // al|ar|ae|k1|cl (5x64), u2(128)@320, v2(128)@448
__device__ __align__(16) float g_den1[N_NODES * 8];
__device__ __align__(16) float g_num1[N_NODES * 8];
__device__ __align__(16) float g_xl2[(size_t)N_NODES * 128];  // 25.6 MB
__device__ __align__(16) float g_xr2[(size_t)N_NODES * 128];  // 25.6 MB
__device__ __align__(16) float g_s[N_NODES];
__device__ __align__(16) float g_t[N_NODES];
// CSR by destination (segments contiguous per node; segment ORDER is arbitrary)
__device__ int   g_cnt[N_NODES];
__device__ int   g_fill[N_NODES];
__device__ int   g_rowbeg[N_NODES];
__device__ int   g_total;
__device__ int   g_esrc[N_EDGES];                             // src node per CSR slot
__device__ __align__(16) float g_ea[N_EDGES];                 // edge_attr per CSR slot

// ---------------- kernel 0: derived rank-1 vectors ----------------
__global__ void k_derive(const float* __restrict__ W_em, const float* __restrict__ b_em,
                         const float* __restrict__ W0,   const float* __restrict__ b0,
                         const float* __restrict__ Wl1,  const float* __restrict__ bl1,
                         const float* __restrict__ Wr1,  const float* __restrict__ br1,
                         const float* __restrict__ We1,  const float* __restrict__ We2) {
    int c = threadIdx.x;  // 0..127
    if (c < 64) {
        float al = 0.f, cl = 0.f, ar = 0.f, cr = 0.f, ae = 0.f, ce = 0.f;
        for (int j = 0; j < 128; j++) {
            float w0 = W0[j], bb = b0[j], we = W_em[j], be = b_em[j];
            float l = Wl1[j * 64 + c], r = Wr1[j * 64 + c], ev = We1[j * 64 + c];
            al = fmaf(w0, l, al); cl = fmaf(bb, l, cl);
            ar = fmaf(w0, r, ar); cr = fmaf(bb, r, cr);
            ae = fmaf(we, ev, ae); ce = fmaf(be, ev, ce);
        }
        cl += bl1[c]; cr += br1[c];
        g_tab[c]       = al;
        g_tab[64 + c]  = ar;
        g_tab[128 + c] = ae;
        g_tab[192 + c] = cl + cr + ce;   // constant inside leaky_relu
        g_tab[256 + c] = cl;             // out1 = al*S1 + cl*S0
    }
    float u = 0.f, v = 0.f;
    for (int j = 0; j < 128; j++) {
        float w = We2[j * 128 + c];
        u = fmaf(W_em[j], w, u);
        v = fmaf(b_em[j], w, v);
    }
    g_tab[320 + c] = u;
    g_tab[448 + c] = v;
}

// ---------------- CSR build ----------------
__global__ void k_zero(int n) {
    int i = blockIdx.x * blockDim.x + threadIdx.x;
    if (i < n) { g_cnt[i] = 0; g_fill[i] = 0; }
    if (i == 0) g_total = 0;
}

__global__ void k_count(const int* __restrict__ ei, int E) {
    int e = blockIdx.x * blockDim.x + threadIdx.x;
    if (e < E) atomicAdd(&g_cnt[ei[E + e]], 1);
}

// warp-aggregated segment allocation: contiguous per-node ranges, order arbitrary.
__global__ __launch_bounds__(256) void k_alloc(int n) {
    int i = blockIdx.x * blockDim.x + threadIdx.x;
    int lane = threadIdx.x & 31;
    int v = (i < n) ? g_cnt[i] : 0;
    int incl = v;
#pragma unroll
    for (int o = 1; o < 32; o <<= 1) {
        int t = __shfl_up_sync(0xffffffffu, incl, o);
        if (lane >= o) incl += t;
    }
    int base = 0;
    if (lane == 31) base = atomicAdd(&g_total, incl);   // one atomic per warp
    base = __shfl_sync(0xffffffffu, base, 31);
    if (i < n) g_rowbeg[i] = base + incl - v;           // exclusive offset within warp chunk
}

__global__ void k_scatter(const int* __restrict__ ei, const float* __restrict__ eattr, int E) {
    int e = blockIdx.x * blockDim.x + threadIdx.x;
    if (e >= E) return;
    int dst = ei[E + e];
    int pos = g_rowbeg[dst] + atomicAdd(&g_fill[dst], 1);
    g_esrc[pos] = ei[e];
    g_ea[pos]   = eattr[e];
}

// ---------------- layer 1 fused: online softmax per (node, head) lane ----------------
__global__ __launch_bounds__(256) void k_seg1(const float* __restrict__ x,
                                              const float* __restrict__ att1, int N) {
    int gl = blockIdx.x * blockDim.x + threadIdx.x;  // lane id in [0, N*8)
    int node = gl >> 3;
    int head = gl & 7;
    if (node >= N) return;
    // coefficients for this head (8 channels) in registers
    float al[8], ar[8], ae[8], k1[8], at[8];
#pragma unroll
    for (int c = 0; c < 8; c++) {
        int i = head * 8 + c;
        al[c] = g_tab[i];
        ar[c] = g_tab[64 + i];
        ae[c] = g_tab[128 + i];
        k1[c] = g_tab[192 + i];
        at[c] = att1[i];
    }
    float xd = x[node];
    int beg = g_rowbeg[node], end = beg + g_cnt[node];
    float mx = -1e30f, den = 0.f, num = 0.f;
    for (int j = beg; j < end; j++) {
        int s = g_esrc[j];
        float ea = g_ea[j];
        float xs = x[s];
        float a = 0.f;
#pragma unroll
        for (int c = 0; c < 8; c++) {
            float z = fmaf(xs, al[c], fmaf(xd, ar[c], fmaf(ea, ae[c], k1[c])));
            z = z > 0.f ? z : 0.2f * z;
            a = fmaf(z, at[c], a);
        }
        float mnew = fmaxf(mx, a);
        float corr = __expf(mx - mnew);   // 0 on first edge (mx=-1e30)
        float ex   = __expf(a - mnew);
        den = den * corr + ex;
        num = num * corr + ex * xs;
        mx = mnew;
    }
    g_den1[node * 8 + head] = den;
    g_num1[node * 8 + head] = num;
}

// ---------------- node pass: h1 = ELU(out1), then xl2/xr2 = h1 @ Wl2/Wr2 ----------------
__global__ __launch_bounds__(256) void k_node1(const float* __restrict__ Wl2, const float* __restrict__ bl2,
                                               const float* __restrict__ Wr2, const float* __restrict__ br2,
                                               const float* __restrict__ bias1, int N) {
    __shared__ float s_h[128 * 64];
    __shared__ float s_al[64], s_cl[64], s_b1[64];
    int tid = threadIdx.x;
    if (tid < 64) { s_al[tid] = g_tab[tid]; s_cl[tid] = g_tab[256 + tid]; s_b1[tid] = bias1[tid]; }
    int half = tid >> 7, k = tid & 127;
    const float* W = half ? Wr2 : Wl2;
    float bcol = half ? br2[k] : bl2[k];
    float wreg[64];
#pragma unroll
    for (int j = 0; j < 64; j++) wreg[j] = W[j * 128 + k];   // weight column in registers
    __syncthreads();
    int n0 = blockIdx.x * 128;
    int nt = min(128, N - n0);
    for (int idx = tid; idx < nt * 64; idx += 256) {
        int nl = idx >> 6, hc = idx & 63, h = hc >> 3;
        int n = n0 + nl;
        float den = g_den1[(size_t)n * 8 + h];
        float dm = fmaxf(den, 1e-16f);
        float S1 = g_num1[(size_t)n * 8 + h] / dm;
        float S0 = den / dm;                                  // 1 if node has edges, else 0
        float o = fmaf(s_al[hc], S1, s_cl[hc] * S0) + s_b1[hc];
        s_h[idx] = o > 0.f ? o : expm1f(o);                   // ELU
    }
    __syncthreads();
    float* dst = half ? g_xr2 : g_xl2;
    for (int nl = 0; nl < nt; nl++) {
        float acc = bcol;
#pragma unroll
        for (int j = 0; j < 64; j++) acc = fmaf(s_h[nl * 64 + j], wreg[j], acc);
        dst[(size_t)(n0 + nl) * 128 + k] = acc;
    }
}

// ---------------- layer 2 fused: warp per node, online softmax, epilogue -> s,t ----------------
__global__ __launch_bounds__(256) void k_seg2(const float* __restrict__ att2,
                                              const float* __restrict__ bias2,
                                              const float* __restrict__ Wd, int N) {
    int wid = (blockIdx.x * blockDim.x + threadIdx.x) >> 5;
    int lane = threadIdx.x & 31;
    if (wid >= N) return;
    int n = wid;
    int c = lane * 4;
    float4 u2  = *(const float4*)&g_tab[320 + c];
    float4 v2  = *(const float4*)&g_tab[448 + c];
    float4 at  = *(const float4*)&att2[c];
    float4 xr  = *(const float4*)&g_xr2[(size_t)n * 128 + c];
    float4 xrv = make_float4(xr.x + v2.x, xr.y + v2.y, xr.z + v2.z, xr.w + v2.w);
    int beg = g_rowbeg[n], end = beg + g_cnt[n];
    float mx = -1e30f, den = 0.f;
    float4 acc = make_float4(0.f, 0.f, 0.f, 0.f);
    for (int j = beg; j < end; j++) {
        int s = g_esrc[j];          // broadcast loads (same addr across warp)
        float ea = g_ea[j];
        float4 xl = *(const float4*)&g_xl2[(size_t)s * 128 + c];
        float z0 = xl.x + fmaf(ea, u2.x, xrv.x); z0 = z0 > 0.f ? z0 : 0.2f * z0;
        float z1 = xl.y + fmaf(ea, u2.y, xrv.y); z1 = z1 > 0.f ? z1 : 0.2f * z1;
        float z2 = xl.z + fmaf(ea, u2.z, xrv.z); z2 = z2 > 0.f ? z2 : 0.2f * z2;
        float z3 = xl.w + fmaf(ea, u2.w, xrv.w); z3 = z3 > 0.f ? z3 : 0.2f * z3;
        float p = fmaf(z0, at.x, fmaf(z1, at.y, fmaf(z2, at.z, z3 * at.w)));
#pragma unroll
        for (int o = 16; o > 0; o >>= 1) p += __shfl_xor_sync(0xffffffffu, p, o);
        float mnew = fmaxf(mx, p);
        float corr = __expf(mx - mnew);
        float ex   = __expf(p - mnew);
        den   = den * corr + ex;
        acc.x = fmaf(acc.x, corr, ex * xl.x);
        acc.y = fmaf(acc.y, corr, ex * xl.y);
        acc.z = fmaf(acc.z, corr, ex * xl.z);
        acc.w = fmaf(acc.w, corr, ex * xl.w);
        mx = mnew;
    }
    float inv = 1.f / fmaxf(den, 1e-16f);
    float4 b2 = *(const float4*)&bias2[c];
    float4 w0 = *(const float4*)&Wd[c];
    float4 w1 = *(const float4*)&Wd[128 + c];
    float h0 = fmaf(acc.x, inv, b2.x), h1 = fmaf(acc.y, inv, b2.y);
    float h2 = fmaf(acc.z, inv, b2.z), h3 = fmaf(acc.w, inv, b2.w);
    float sa = fmaf(h0, w0.x, fmaf(h1, w0.y, fmaf(h2, w0.z, h3 * w0.w)));
    float ta = fmaf(h0, w1.x, fmaf(h1, w1.y, fmaf(h2, w1.z, h3 * w1.w)));
#pragma unroll
    for (int o = 16; o > 0; o >>= 1) {
        sa += __shfl_xor_sync(0xffffffffu, sa, o);
        ta += __shfl_xor_sync(0xffffffffu, ta, o);
    }
    if (lane == 0) { g_s[n] = sa; g_t[n] = ta; }
}

// ---------------- final: out[e] = s[src] + t[dst] + bd ----------------
__global__ __launch_bounds__(256) void k_final(const int* __restrict__ ei,
                                               const float* __restrict__ bd,
                                               float* __restrict__ out, int E) {
    int e = blockIdx.x * blockDim.x + threadIdx.x;
    if (e >= E) return;
    out[e] = g_s[ei[e]] + g_t[ei[E + e]] + bd[0];
}

// ---------------- launch ----------------
extern "C" void kernel_launch(void* const* d_in, const int* in_sizes, int n_in,
                              void* d_out, int out_size) {
    const float* x     = (const float*)d_in[0];
    const int*   ei    = (const int*)d_in[1];      // int32 (JAX x64 disabled)
    const float* eattr = (const float*)d_in[2];
    const float* W_em = (const float*)d_in[3];  const float* b_em = (const float*)d_in[4];
    const float* W0   = (const float*)d_in[5];  const float* b0   = (const float*)d_in[6];
    const float* Wl1  = (const float*)d_in[7];  const float* bl1  = (const float*)d_in[8];
    const float* Wr1  = (const float*)d_in[9];  const float* br1  = (const float*)d_in[10];
    const float* We1  = (const float*)d_in[11]; const float* att1 = (const float*)d_in[12];
    const float* bias1= (const float*)d_in[13];
    const float* Wl2  = (const float*)d_in[14]; const float* bl2  = (const float*)d_in[15];
    const float* Wr2  = (const float*)d_in[16]; const float* br2  = (const float*)d_in[17];
    const float* We2  = (const float*)d_in[18]; const float* att2 = (const float*)d_in[19];
    const float* bias2= (const float*)d_in[20];
    const float* Wd   = (const float*)d_in[21]; const float* bd   = (const float*)d_in[22];
    int N = in_sizes[0];          // x is [N,1]
    int E = in_sizes[2];          // edge_attr is [E,1]
    float* out = (float*)d_out;

    k_zero<<<(N + 255) / 256, 256>>>(N);
    k_derive<<<1, 128>>>(W_em, b_em, W0, b0, Wl1, bl1, Wr1, br1, We1, We2);
    k_count<<<(E + 255) / 256, 256>>>(ei, E);
    k_alloc<<<(N + 255) / 256, 256>>>(N);
    k_scatter<<<(E + 255) / 256, 256>>>(ei, eattr, E);
    k_seg1<<<(N * 8 + 255) / 256, 256>>>(x, att1, N);
    k_node1<<<(N + 127) / 128, 256>>>(Wl2, bl2, Wr2, br2, bias1, N);
    k_seg2<<<(N + 7) / 8, 256>>>(att2, bias2, Wd, N);
    k_final<<<(E + 255) / 256, 256>>>(ei, bd, out, E);
}